// round 1
// baseline (speedup 1.0000x reference)
#include <cuda_runtime.h>
#include <math.h>

#define B_   4
#define C_   256
#define H_   32
#define W_   32
#define N_   1024
#define NH_  8
#define HC_  32
#define NG_  4
#define GC_  64
#define BG_  16
#define SCALE_ 0.17677669529663687f   /* 32^-0.5 */
#define EPS_  1e-5f

// ---- scratch (device globals; no allocations allowed) ----
__device__ float g_q  [B_*C_*N_];
__device__ float g_pos[BG_*N_*2];
__device__ float g_xs [B_*C_*N_];
__device__ float g_k  [B_*C_*N_];
__device__ float g_v  [B_*C_*N_];
__device__ float g_attn[(size_t)B_*NH_*N_*N_];   // 134 MB
__device__ float g_o  [B_*C_*N_];

// ============================================================
// Generic projection GEMM: Y[b,o,p] = sum_i W[o,i]*X[b,i,p] + bias[o]
// W: (C,C) row-major, X/Y: (B,C,N). Tiles 32x32x32.
// ============================================================
__global__ void gemm_proj(const float* __restrict__ Wt, const float* __restrict__ bias,
                          const float* __restrict__ X, float* __restrict__ Y) {
    __shared__ float Ws[32][33], Xs[32][33];
    int tx = threadIdx.x, ty = threadIdx.y;
    int p0 = blockIdx.x * 32, o0 = blockIdx.y * 32, b = blockIdx.z;
    float acc = 0.f;
    for (int kt = 0; kt < C_; kt += 32) {
        Ws[ty][tx] = Wt[(o0 + ty) * C_ + kt + tx];
        Xs[ty][tx] = X[(size_t)b * C_ * N_ + (size_t)(kt + ty) * N_ + p0 + tx];
        __syncthreads();
#pragma unroll
        for (int k = 0; k < 32; k++) acc += Ws[ty][k] * Xs[k][tx];
        __syncthreads();
    }
    Y[(size_t)b * C_ * N_ + (size_t)(o0 + ty) * N_ + p0 + tx] = acc + bias[o0 + ty];
}

// ============================================================
// Offset network: depthwise 3x3 conv -> LN(channels) -> GELU -> pointwise(2)
// -> tanh*range + ref  => g_pos (BG, N, 2) as (y, x)
// ============================================================
__global__ void offset_kernel(const float* __restrict__ dw_w, const float* __restrict__ dw_b,
                              const float* __restrict__ ln_w, const float* __restrict__ ln_b,
                              const float* __restrict__ pw_w) {
    int idx = blockIdx.x * blockDim.x + threadIdx.x;   // bg*N + p
    if (idx >= BG_ * N_) return;
    int bg = idx >> 10, p = idx & (N_ - 1);
    int h = p >> 5, w = p & 31;
    int b = bg >> 2, g = bg & 3;
    const float* qbase = g_q + (size_t)b * C_ * N_ + (size_t)g * GC_ * N_;

    float x[GC_];
    float s1 = 0.f;
    for (int c = 0; c < GC_; c++) {
        const float* qc = qbase + c * N_;
        float t = dw_b[c];
#pragma unroll
        for (int dy = 0; dy < 3; dy++) {
            int hh = h + dy - 1;
            if (hh < 0 || hh >= H_) continue;
#pragma unroll
            for (int dx = 0; dx < 3; dx++) {
                int ww = w + dx - 1;
                if (ww < 0 || ww >= W_) continue;
                t += dw_w[c * 9 + dy * 3 + dx] * qc[hh * W_ + ww];
            }
        }
        x[c] = t; s1 += t;
    }
    float mu = s1 * (1.f / GC_);
    float s2 = 0.f;
    for (int c = 0; c < GC_; c++) { float d = x[c] - mu; s2 += d * d; }
    float rinv = rsqrtf(s2 * (1.f / GC_) + EPS_);
    float off0 = 0.f, off1 = 0.f;
    for (int c = 0; c < GC_; c++) {
        float xn  = (x[c] - mu) * rinv * ln_w[c] + ln_b[c];
        float gel = 0.5f * xn * (1.f + erff(xn * 0.7071067811865476f));
        off0 += pw_w[c] * gel;          // y
        off1 += pw_w[GC_ + c] * gel;    // x
    }
    const float rng = 4.0f / 31.0f;
    float py = tanhf(off0) * rng + ((0.5f + (float)h) / 31.f) * 2.f - 1.f;
    float px = tanhf(off1) * rng + ((0.5f + (float)w) / 31.f) * 2.f - 1.f;
    g_pos[idx * 2 + 0] = py;
    g_pos[idx * 2 + 1] = px;
}

// ============================================================
// Deformable bilinear sampling of kv features (align_corners, zeros pad)
// one block per (bg,p), 64 threads over the group channels.
// ============================================================
__global__ void sample_kernel(const float* __restrict__ kv) {
    int blk = blockIdx.x;                 // bg*N + p
    int c = threadIdx.x;
    int bg = blk >> 10, p = blk & (N_ - 1);
    int b = bg >> 2, g = bg & 3;
    float py = g_pos[blk * 2 + 0], px = g_pos[blk * 2 + 1];
    float ix = (px + 1.f) * 15.5f;        // *0.5*(W-1)
    float iy = (py + 1.f) * 15.5f;
    float x0f = floorf(ix), y0f = floorf(iy);
    float wx1 = ix - x0f, wx0 = 1.f - wx1;
    float wy1 = iy - y0f, wy0 = 1.f - wy1;
    int x0 = (int)x0f, y0 = (int)y0f;
    const float* src = kv + ((size_t)b * C_ + g * GC_ + c) * N_;
    float acc = 0.f;
#pragma unroll
    for (int cy = 0; cy < 2; cy++) {
        int yy = y0 + cy;
        if (yy < 0 || yy >= H_) continue;
        float wy = cy ? wy1 : wy0;
#pragma unroll
        for (int cx = 0; cx < 2; cx++) {
            int xx = x0 + cx;
            if (xx < 0 || xx >= W_) continue;
            acc += wy * (cx ? wx1 : wx0) * src[yy * W_ + xx];
        }
    }
    g_xs[((size_t)b * C_ + g * GC_ + c) * N_ + p] = acc;
}

// ============================================================
// Attention scores: attn[b,h,m,n] = SCALE * sum_c q[.,c,m]*k[.,c,n] + rpe_bias
// bias via bilinear sample of rpe_table[h] (63x63, align_corners, zeros pad)
// ============================================================
__global__ void score_kernel(const float* __restrict__ rpe) {
    int bh = blockIdx.z;                   // b*8 + h
    int b = bh >> 3, hd = bh & 7;
    int m0 = blockIdx.y * 32, n0 = blockIdx.x * 32;
    int tx = threadIdx.x, ty = threadIdx.y;
    __shared__ float qs[32][33], ks[32][33];
    __shared__ float posy[32], posx[32];

    const float* qb = g_q + ((size_t)b * C_ + hd * HC_) * N_;
    const float* kb = g_k + ((size_t)b * C_ + hd * HC_) * N_;
    qs[ty][tx] = qb[(size_t)ty * N_ + m0 + tx];
    ks[ty][tx] = kb[(size_t)ty * N_ + n0 + tx];
    int bg = b * NG_ + (hd >> 1);
    if (ty == 0) {
        posy[tx] = g_pos[(bg * N_ + n0 + tx) * 2 + 0];
        posx[tx] = g_pos[(bg * N_ + n0 + tx) * 2 + 1];
    }
    __syncthreads();

    float acc = 0.f;
#pragma unroll
    for (int c = 0; c < 32; c++) acc += qs[c][ty] * ks[c][tx];
    acc *= SCALE_;

    int m = m0 + ty;
    float gy = (float)(m >> 5) * (2.f / 31.f) - 1.f;
    float gx = (float)(m & 31) * (2.f / 31.f) - 1.f;
    float dyv = (gy - posy[tx]) * 0.5f;
    float dxv = (gx - posx[tx]) * 0.5f;
    float ix = (dxv + 1.f) * 31.f;         // *0.5*(63-1)
    float iy = (dyv + 1.f) * 31.f;
    float x0f = floorf(ix), y0f = floorf(iy);
    float wx1 = ix - x0f, wx0 = 1.f - wx1;
    float wy1 = iy - y0f, wy0 = 1.f - wy1;
    int x0 = (int)x0f, y0 = (int)y0f;
    const float* tb = rpe + hd * 63 * 63;
    float bias = 0.f;
#pragma unroll
    for (int cy = 0; cy < 2; cy++) {
        int yy = y0 + cy;
        if (yy < 0 || yy > 62) continue;
        float wy = cy ? wy1 : wy0;
#pragma unroll
        for (int cx = 0; cx < 2; cx++) {
            int xx = x0 + cx;
            if (xx < 0 || xx > 62) continue;
            bias += wy * (cx ? wx1 : wx0) * tb[yy * 63 + xx];
        }
    }
    g_attn[(size_t)bh * N_ * N_ + (size_t)m * N_ + n0 + tx] = acc + bias;
}

// ============================================================
// Row softmax over last dim (1024), one block (256 thr) per row.
// ============================================================
__global__ void softmax_kernel() {
    size_t row = blockIdx.x;
    float* a = g_attn + row * N_;
    int t = threadIdx.x;
    float v[4];
    float m = -1e30f;
#pragma unroll
    for (int i = 0; i < 4; i++) { v[i] = a[t + i * 256]; m = fmaxf(m, v[i]); }
    __shared__ float red[8];
#pragma unroll
    for (int o = 16; o; o >>= 1) m = fmaxf(m, __shfl_xor_sync(0xffffffffu, m, o));
    if ((t & 31) == 0) red[t >> 5] = m;
    __syncthreads();
    if (t == 0) { float mm = red[0]; for (int i = 1; i < 8; i++) mm = fmaxf(mm, red[i]); red[0] = mm; }
    __syncthreads();
    m = red[0];
    __syncthreads();
    float s = 0.f;
#pragma unroll
    for (int i = 0; i < 4; i++) { v[i] = expf(v[i] - m); s += v[i]; }
#pragma unroll
    for (int o = 16; o; o >>= 1) s += __shfl_xor_sync(0xffffffffu, s, o);
    if ((t & 31) == 0) red[t >> 5] = s;
    __syncthreads();
    if (t == 0) { float ss = red[0]; for (int i = 1; i < 8; i++) ss += red[i]; red[0] = ss; }
    __syncthreads();
    float r = 1.f / red[0];
#pragma unroll
    for (int i = 0; i < 4; i++) a[t + i * 256] = v[i] * r;
}

// ============================================================
// AV: g_o[b, h*32+c, m] = sum_n attn[b,h,m,n] * v[b,h*32+c,n]
// ============================================================
__global__ void av_kernel() {
    int bh = blockIdx.y;
    int m0 = blockIdx.x * 32;
    int b = bh >> 3, hd = bh & 7;
    int tx = threadIdx.x, ty = threadIdx.y;
    __shared__ float as[32][33], vs[32][33];
    const float* arow = g_attn + (size_t)bh * N_ * N_;
    const float* vb = g_v + ((size_t)b * C_ + hd * HC_) * N_;
    float acc = 0.f;
    for (int n0 = 0; n0 < N_; n0 += 32) {
        as[ty][tx] = arow[(size_t)(m0 + ty) * N_ + n0 + tx];
        vs[ty][tx] = vb[(size_t)ty * N_ + n0 + tx];
        __syncthreads();
#pragma unroll
        for (int k = 0; k < 32; k++) acc += as[tx][k] * vs[ty][k];
        __syncthreads();
    }
    // output: (m = m0+tx coalesced, channel = ty)
    g_o[((size_t)b * C_ + hd * HC_ + ty) * N_ + m0 + tx] = acc;
}

// ============================================================
extern "C" void kernel_launch(void* const* d_in, const int* in_sizes, int n_in,
                              void* d_out, int out_size) {
    const float* q_feat = (const float*)d_in[0];
    const float* kv_feat = (const float*)d_in[1];
    const float* Wq = (const float*)d_in[2];
    const float* bq = (const float*)d_in[3];
    const float* Wk = (const float*)d_in[4];
    const float* bk = (const float*)d_in[5];
    const float* Wv = (const float*)d_in[6];
    const float* bv = (const float*)d_in[7];
    const float* Wo = (const float*)d_in[8];
    const float* bo = (const float*)d_in[9];
    const float* dw_w = (const float*)d_in[10];
    const float* dw_b = (const float*)d_in[11];
    const float* ln_w = (const float*)d_in[12];
    const float* ln_b = (const float*)d_in[13];
    const float* pw_w = (const float*)d_in[14];
    const float* rpe  = (const float*)d_in[15];
    float* out = (float*)d_out;

    float *gq, *gxs, *gk, *gv, *go;
    cudaGetSymbolAddress((void**)&gq,  g_q);
    cudaGetSymbolAddress((void**)&gxs, g_xs);
    cudaGetSymbolAddress((void**)&gk,  g_k);
    cudaGetSymbolAddress((void**)&gv,  g_v);
    cudaGetSymbolAddress((void**)&go,  g_o);

    dim3 tb(32, 32);
    dim3 gemm_grid(N_ / 32, C_ / 32, B_);

    // 1. q projection
    gemm_proj<<<gemm_grid, tb>>>(Wq, bq, q_feat, gq);
    // 2. offset network -> pos
    offset_kernel<<<(BG_ * N_ + 255) / 256, 256>>>(dw_w, dw_b, ln_w, ln_b, pw_w);
    // 3. deformable sampling of kv
    sample_kernel<<<BG_ * N_, GC_>>>(kv_feat);
    // 4. k, v projections
    gemm_proj<<<gemm_grid, tb>>>(Wk, bk, gxs, gk);
    gemm_proj<<<gemm_grid, tb>>>(Wv, bv, gxs, gv);
    // 5. scores + rpe bias
    score_kernel<<<dim3(N_ / 32, N_ / 32, B_ * NH_), tb>>>(rpe);
    // 6. softmax
    softmax_kernel<<<B_ * NH_ * N_, 256>>>();
    // 7. attn @ v
    av_kernel<<<dim3(N_ / 32, B_ * NH_), tb>>>();
    // 8. output projection
    gemm_proj<<<gemm_grid, tb>>>(Wo, bo, go, out);
}

// round 2
// speedup vs baseline: 1.0016x; 1.0016x over previous
#include <cuda_runtime.h>
#include <math.h>

#define B_   4
#define C_   256
#define H_   32
#define W_   32
#define N_   1024
#define NH_  8
#define HC_  32
#define NG_  4
#define GC_  64
#define BG_  16
#define SCALE_ 0.17677669529663687f   /* 32^-0.5 */
#define EPS_  1e-5f

// ---- scratch (device globals; no allocations allowed) ----
__device__ float g_q  [B_*C_*N_];
__device__ float g_pos[BG_*N_*2];
__device__ float g_xs [B_*C_*N_];
__device__ float g_k  [B_*C_*N_];
__device__ float g_v  [B_*C_*N_];
__device__ float g_attn[(size_t)B_*NH_*N_*N_];   // 134 MB
__device__ float g_o  [B_*C_*N_];

// ============================================================
// Generic projection GEMM: Y[b,o,p] = sum_i W[o,i]*X[b,i,p] + bias[o]
// W: (C,C) row-major, X/Y: (B,C,N). Tiles 32x32x32.
// ============================================================
__global__ void gemm_proj(const float* __restrict__ Wt, const float* __restrict__ bias,
                          const float* __restrict__ X, float* __restrict__ Y) {
    __shared__ float Ws[32][33], Xs[32][33];
    int tx = threadIdx.x, ty = threadIdx.y;
    int p0 = blockIdx.x * 32, o0 = blockIdx.y * 32, b = blockIdx.z;
    float acc = 0.f;
    for (int kt = 0; kt < C_; kt += 32) {
        Ws[ty][tx] = Wt[(o0 + ty) * C_ + kt + tx];
        Xs[ty][tx] = X[(size_t)b * C_ * N_ + (size_t)(kt + ty) * N_ + p0 + tx];
        __syncthreads();
#pragma unroll
        for (int k = 0; k < 32; k++) acc += Ws[ty][k] * Xs[k][tx];
        __syncthreads();
    }
    Y[(size_t)b * C_ * N_ + (size_t)(o0 + ty) * N_ + p0 + tx] = acc + bias[o0 + ty];
}

// ============================================================
// Offset network: depthwise 3x3 conv -> LN(channels) -> GELU -> pointwise(2)
// -> tanh*range + ref  => g_pos (BG, N, 2) as (y, x)
// ============================================================
__global__ void offset_kernel(const float* __restrict__ dw_w, const float* __restrict__ dw_b,
                              const float* __restrict__ ln_w, const float* __restrict__ ln_b,
                              const float* __restrict__ pw_w) {
    int idx = blockIdx.x * blockDim.x + threadIdx.x;   // bg*N + p
    if (idx >= BG_ * N_) return;
    int bg = idx >> 10, p = idx & (N_ - 1);
    int h = p >> 5, w = p & 31;
    int b = bg >> 2, g = bg & 3;
    const float* qbase = g_q + (size_t)b * C_ * N_ + (size_t)g * GC_ * N_;

    float x[GC_];
    float s1 = 0.f;
    for (int c = 0; c < GC_; c++) {
        const float* qc = qbase + c * N_;
        float t = dw_b[c];
#pragma unroll
        for (int dy = 0; dy < 3; dy++) {
            int hh = h + dy - 1;
            if (hh < 0 || hh >= H_) continue;
#pragma unroll
            for (int dx = 0; dx < 3; dx++) {
                int ww = w + dx - 1;
                if (ww < 0 || ww >= W_) continue;
                t += dw_w[c * 9 + dy * 3 + dx] * qc[hh * W_ + ww];
            }
        }
        x[c] = t; s1 += t;
    }
    float mu = s1 * (1.f / GC_);
    float s2 = 0.f;
    for (int c = 0; c < GC_; c++) { float d = x[c] - mu; s2 += d * d; }
    float rinv = rsqrtf(s2 * (1.f / GC_) + EPS_);
    float off0 = 0.f, off1 = 0.f;
    for (int c = 0; c < GC_; c++) {
        float xn  = (x[c] - mu) * rinv * ln_w[c] + ln_b[c];
        float gel = 0.5f * xn * (1.f + erff(xn * 0.7071067811865476f));
        off0 += pw_w[c] * gel;          // y
        off1 += pw_w[GC_ + c] * gel;    // x
    }
    const float rng = 4.0f / 31.0f;
    float py = tanhf(off0) * rng + ((0.5f + (float)h) / 31.f) * 2.f - 1.f;
    float px = tanhf(off1) * rng + ((0.5f + (float)w) / 31.f) * 2.f - 1.f;
    g_pos[idx * 2 + 0] = py;
    g_pos[idx * 2 + 1] = px;
}

// ============================================================
// Deformable bilinear sampling of kv features (align_corners, zeros pad)
// one block per (bg,p), 64 threads over the group channels.
// ============================================================
__global__ void sample_kernel(const float* __restrict__ kv) {
    int blk = blockIdx.x;                 // bg*N + p
    int c = threadIdx.x;
    int bg = blk >> 10, p = blk & (N_ - 1);
    int b = bg >> 2, g = bg & 3;
    float py = g_pos[blk * 2 + 0], px = g_pos[blk * 2 + 1];
    float ix = (px + 1.f) * 15.5f;        // *0.5*(W-1)
    float iy = (py + 1.f) * 15.5f;
    float x0f = floorf(ix), y0f = floorf(iy);
    float wx1 = ix - x0f, wx0 = 1.f - wx1;
    float wy1 = iy - y0f, wy0 = 1.f - wy1;
    int x0 = (int)x0f, y0 = (int)y0f;
    const float* src = kv + ((size_t)b * C_ + g * GC_ + c) * N_;
    float acc = 0.f;
#pragma unroll
    for (int cy = 0; cy < 2; cy++) {
        int yy = y0 + cy;
        if (yy < 0 || yy >= H_) continue;
        float wy = cy ? wy1 : wy0;
#pragma unroll
        for (int cx = 0; cx < 2; cx++) {
            int xx = x0 + cx;
            if (xx < 0 || xx >= W_) continue;
            acc += wy * (cx ? wx1 : wx0) * src[yy * W_ + xx];
        }
    }
    g_xs[((size_t)b * C_ + g * GC_ + c) * N_ + p] = acc;
}

// ============================================================
// Attention scores: attn[b,h,m,n] = SCALE * sum_c q[.,c,m]*k[.,c,n] + rpe_bias
// bias via bilinear sample of rpe_table[h] (63x63, align_corners, zeros pad)
// ============================================================
__global__ void score_kernel(const float* __restrict__ rpe) {
    int bh = blockIdx.z;                   // b*8 + h
    int b = bh >> 3, hd = bh & 7;
    int m0 = blockIdx.y * 32, n0 = blockIdx.x * 32;
    int tx = threadIdx.x, ty = threadIdx.y;
    __shared__ float qs[32][33], ks[32][33];
    __shared__ float posy[32], posx[32];

    const float* qb = g_q + ((size_t)b * C_ + hd * HC_) * N_;
    const float* kb = g_k + ((size_t)b * C_ + hd * HC_) * N_;
    qs[ty][tx] = qb[(size_t)ty * N_ + m0 + tx];
    ks[ty][tx] = kb[(size_t)ty * N_ + n0 + tx];
    int bg = b * NG_ + (hd >> 1);
    if (ty == 0) {
        posy[tx] = g_pos[(bg * N_ + n0 + tx) * 2 + 0];
        posx[tx] = g_pos[(bg * N_ + n0 + tx) * 2 + 1];
    }
    __syncthreads();

    float acc = 0.f;
#pragma unroll
    for (int c = 0; c < 32; c++) acc += qs[c][ty] * ks[c][tx];
    acc *= SCALE_;

    int m = m0 + ty;
    float gy = (float)(m >> 5) * (2.f / 31.f) - 1.f;
    float gx = (float)(m & 31) * (2.f / 31.f) - 1.f;
    float dyv = (gy - posy[tx]) * 0.5f;
    float dxv = (gx - posx[tx]) * 0.5f;
    float ix = (dxv + 1.f) * 31.f;         // *0.5*(63-1)
    float iy = (dyv + 1.f) * 31.f;
    float x0f = floorf(ix), y0f = floorf(iy);
    float wx1 = ix - x0f, wx0 = 1.f - wx1;
    float wy1 = iy - y0f, wy0 = 1.f - wy1;
    int x0 = (int)x0f, y0 = (int)y0f;
    const float* tb = rpe + hd * 63 * 63;
    float bias = 0.f;
#pragma unroll
    for (int cy = 0; cy < 2; cy++) {
        int yy = y0 + cy;
        if (yy < 0 || yy > 62) continue;
        float wy = cy ? wy1 : wy0;
#pragma unroll
        for (int cx = 0; cx < 2; cx++) {
            int xx = x0 + cx;
            if (xx < 0 || xx > 62) continue;
            bias += wy * (cx ? wx1 : wx0) * tb[yy * 63 + xx];
        }
    }
    g_attn[(size_t)bh * N_ * N_ + (size_t)m * N_ + n0 + tx] = acc + bias;
}

// ============================================================
// Row softmax over last dim (1024), one block (256 thr) per row.
// ============================================================
__global__ void softmax_kernel() {
    size_t row = blockIdx.x;
    float* a = g_attn + row * N_;
    int t = threadIdx.x;
    float v[4];
    float m = -1e30f;
#pragma unroll
    for (int i = 0; i < 4; i++) { v[i] = a[t + i * 256]; m = fmaxf(m, v[i]); }
    __shared__ float red[8];
#pragma unroll
    for (int o = 16; o; o >>= 1) m = fmaxf(m, __shfl_xor_sync(0xffffffffu, m, o));
    if ((t & 31) == 0) red[t >> 5] = m;
    __syncthreads();
    if (t == 0) { float mm = red[0]; for (int i = 1; i < 8; i++) mm = fmaxf(mm, red[i]); red[0] = mm; }
    __syncthreads();
    m = red[0];
    __syncthreads();
    float s = 0.f;
#pragma unroll
    for (int i = 0; i < 4; i++) { v[i] = expf(v[i] - m); s += v[i]; }
#pragma unroll
    for (int o = 16; o; o >>= 1) s += __shfl_xor_sync(0xffffffffu, s, o);
    if ((t & 31) == 0) red[t >> 5] = s;
    __syncthreads();
    if (t == 0) { float ss = red[0]; for (int i = 1; i < 8; i++) ss += red[i]; red[0] = ss; }
    __syncthreads();
    float r = 1.f / red[0];
#pragma unroll
    for (int i = 0; i < 4; i++) a[t + i * 256] = v[i] * r;
}

// ============================================================
// AV: g_o[b, h*32+c, m] = sum_n attn[b,h,m,n] * v[b,h*32+c,n]
// ============================================================
__global__ void av_kernel() {
    int bh = blockIdx.y;
    int m0 = blockIdx.x * 32;
    int b = bh >> 3, hd = bh & 7;
    int tx = threadIdx.x, ty = threadIdx.y;
    __shared__ float as[32][33], vs[32][33];
    const float* arow = g_attn + (size_t)bh * N_ * N_;
    const float* vb = g_v + ((size_t)b * C_ + hd * HC_) * N_;
    float acc = 0.f;
    for (int n0 = 0; n0 < N_; n0 += 32) {
        as[ty][tx] = arow[(size_t)(m0 + ty) * N_ + n0 + tx];
        vs[ty][tx] = vb[(size_t)ty * N_ + n0 + tx];
        __syncthreads();
#pragma unroll
        for (int k = 0; k < 32; k++) acc += as[tx][k] * vs[ty][k];
        __syncthreads();
    }
    // output: (m = m0+tx coalesced, channel = ty)
    g_o[((size_t)b * C_ + hd * HC_ + ty) * N_ + m0 + tx] = acc;
}

// ============================================================
extern "C" void kernel_launch(void* const* d_in, const int* in_sizes, int n_in,
                              void* d_out, int out_size) {
    const float* q_feat = (const float*)d_in[0];
    const float* kv_feat = (const float*)d_in[1];
    const float* Wq = (const float*)d_in[2];
    const float* bq = (const float*)d_in[3];
    const float* Wk = (const float*)d_in[4];
    const float* bk = (const float*)d_in[5];
    const float* Wv = (const float*)d_in[6];
    const float* bv = (const float*)d_in[7];
    const float* Wo = (const float*)d_in[8];
    const float* bo = (const float*)d_in[9];
    const float* dw_w = (const float*)d_in[10];
    const float* dw_b = (const float*)d_in[11];
    const float* ln_w = (const float*)d_in[12];
    const float* ln_b = (const float*)d_in[13];
    const float* pw_w = (const float*)d_in[14];
    const float* rpe  = (const float*)d_in[15];
    float* out = (float*)d_out;

    float *gq, *gxs, *gk, *gv, *go;
    cudaGetSymbolAddress((void**)&gq,  g_q);
    cudaGetSymbolAddress((void**)&gxs, g_xs);
    cudaGetSymbolAddress((void**)&gk,  g_k);
    cudaGetSymbolAddress((void**)&gv,  g_v);
    cudaGetSymbolAddress((void**)&go,  g_o);

    dim3 tb(32, 32);
    dim3 gemm_grid(N_ / 32, C_ / 32, B_);

    // 1. q projection
    gemm_proj<<<gemm_grid, tb>>>(Wq, bq, q_feat, gq);
    // 2. offset network -> pos
    offset_kernel<<<(BG_ * N_ + 255) / 256, 256>>>(dw_w, dw_b, ln_w, ln_b, pw_w);
    // 3. deformable sampling of kv
    sample_kernel<<<BG_ * N_, GC_>>>(kv_feat);
    // 4. k, v projections
    gemm_proj<<<gemm_grid, tb>>>(Wk, bk, gxs, gk);
    gemm_proj<<<gemm_grid, tb>>>(Wv, bv, gxs, gv);
    // 5. scores + rpe bias
    score_kernel<<<dim3(N_ / 32, N_ / 32, B_ * NH_), tb>>>(rpe);
    // 6. softmax
    softmax_kernel<<<B_ * NH_ * N_, 256>>>();
    // 7. attn @ v
    av_kernel<<<dim3(N_ / 32, B_ * NH_), tb>>>();
    // 8. output projection
    gemm_proj<<<gemm_grid, tb>>>(Wo, bo, go, out);
}

// round 3
// speedup vs baseline: 2.5425x; 2.5385x over previous
#include <cuda_runtime.h>
#include <math.h>

#define B_   4
#define C_   256
#define H_   32
#define W_   32
#define N_   1024
#define NH_  8
#define HC_  32
#define NG_  4
#define GC_  64
#define BG_  16
#define SCALE_ 0.17677669529663687f   /* 32^-0.5 */
#define EPS_  1e-5f

// ---- scratch (device globals; no allocations allowed) ----
__device__ float g_q  [B_*C_*N_];
__device__ float g_pos[BG_*N_*2];
__device__ float g_xs [B_*C_*N_];
__device__ float g_k  [B_*C_*N_];
__device__ float g_v  [B_*C_*N_];
__device__ float g_o  [B_*C_*N_];

// Fast exp on the FMA pipe (avoids MUFU throughput wall).
// Accurate to ~2e-6 rel; input effectively <= 0 in softmax use.
__device__ __forceinline__ float fexp(float x) {
    float t = fmaxf(x * 1.4426950408889634f, -126.0f);
    float n = rintf(t);
    float f = t - n;
    float p =             1.3333558146e-3f;
    p = fmaf(p, f, 9.6181291794e-3f);
    p = fmaf(p, f, 5.5504108625e-2f);
    p = fmaf(p, f, 2.4022650696e-1f);
    p = fmaf(p, f, 6.9314718056e-1f);
    p = fmaf(p, f, 1.0f);
    return p * __int_as_float(((int)n + 127) << 23);
}

// ============================================================
// Projection GEMM: Y[b,o,p] = sum_i W[o,i]*X[b,i,p] + bias[o]
// 64x64 tile, 256 threads, 4x4 register tile per thread.
// ============================================================
__global__ __launch_bounds__(256) void gemm_proj(
        const float* __restrict__ Wt, const float* __restrict__ bias,
        const float* __restrict__ X, float* __restrict__ Y) {
    __shared__ float Ws[16][68];   // [k][o]
    __shared__ float Xs[16][68];   // [k][p]
    int tid = threadIdx.x;
    int tx = tid & 15, ty = tid >> 4;
    int p0 = blockIdx.x << 6, o0 = blockIdx.y << 6, b = blockIdx.z;
    const float* Xb = X + (size_t)b * C_ * N_;
    float acc[4][4] = {};
    int lk = ty;            // k row this thread loads
    int lc = tx << 2;       // col base this thread loads

    for (int kt = 0; kt < C_; kt += 16) {
#pragma unroll
        for (int j = 0; j < 4; j++)
            Ws[lk][lc + j] = Wt[(size_t)(o0 + lc + j) * C_ + kt + lk];
        *(float4*)&Xs[lk][lc] =
            *(const float4*)&Xb[(size_t)(kt + lk) * N_ + p0 + lc];
        __syncthreads();
#pragma unroll
        for (int kk = 0; kk < 16; kk++) {
            float4 wv = *(const float4*)&Ws[kk][ty << 2];
            float4 xv = *(const float4*)&Xs[kk][tx << 2];
            acc[0][0] = fmaf(wv.x, xv.x, acc[0][0]);
            acc[0][1] = fmaf(wv.x, xv.y, acc[0][1]);
            acc[0][2] = fmaf(wv.x, xv.z, acc[0][2]);
            acc[0][3] = fmaf(wv.x, xv.w, acc[0][3]);
            acc[1][0] = fmaf(wv.y, xv.x, acc[1][0]);
            acc[1][1] = fmaf(wv.y, xv.y, acc[1][1]);
            acc[1][2] = fmaf(wv.y, xv.z, acc[1][2]);
            acc[1][3] = fmaf(wv.y, xv.w, acc[1][3]);
            acc[2][0] = fmaf(wv.z, xv.x, acc[2][0]);
            acc[2][1] = fmaf(wv.z, xv.y, acc[2][1]);
            acc[2][2] = fmaf(wv.z, xv.z, acc[2][2]);
            acc[2][3] = fmaf(wv.z, xv.w, acc[2][3]);
            acc[3][0] = fmaf(wv.w, xv.x, acc[3][0]);
            acc[3][1] = fmaf(wv.w, xv.y, acc[3][1]);
            acc[3][2] = fmaf(wv.w, xv.z, acc[3][2]);
            acc[3][3] = fmaf(wv.w, xv.w, acc[3][3]);
        }
        __syncthreads();
    }
#pragma unroll
    for (int i = 0; i < 4; i++) {
        int o = o0 + (ty << 2) + i;
        float bs = bias[o];
        float4 r = make_float4(acc[i][0] + bs, acc[i][1] + bs,
                               acc[i][2] + bs, acc[i][3] + bs);
        *(float4*)&Y[(size_t)(b * C_ + o) * N_ + p0 + (tx << 2)] = r;
    }
}

// ============================================================
// Offset network: depthwise 3x3 -> LN -> GELU -> pointwise(2)
// -> tanh*range + ref  => g_pos (BG, N, 2) as (y, x)
// ============================================================
__global__ void offset_kernel(const float* __restrict__ dw_w, const float* __restrict__ dw_b,
                              const float* __restrict__ ln_w, const float* __restrict__ ln_b,
                              const float* __restrict__ pw_w) {
    int idx = blockIdx.x * blockDim.x + threadIdx.x;   // bg*N + p
    if (idx >= BG_ * N_) return;
    int bg = idx >> 10, p = idx & (N_ - 1);
    int h = p >> 5, w = p & 31;
    int b = bg >> 2, g = bg & 3;
    const float* qbase = g_q + (size_t)b * C_ * N_ + (size_t)g * GC_ * N_;

    float x[GC_];
    float s1 = 0.f;
#pragma unroll
    for (int c = 0; c < GC_; c++) {
        const float* qc = qbase + c * N_;
        float t = dw_b[c];
#pragma unroll
        for (int dy = 0; dy < 3; dy++) {
            int hh = h + dy - 1;
            if (hh < 0 || hh >= H_) continue;
#pragma unroll
            for (int dx = 0; dx < 3; dx++) {
                int ww = w + dx - 1;
                if (ww < 0 || ww >= W_) continue;
                t += dw_w[c * 9 + dy * 3 + dx] * qc[hh * W_ + ww];
            }
        }
        x[c] = t; s1 += t;
    }
    float mu = s1 * (1.f / GC_);
    float s2 = 0.f;
#pragma unroll
    for (int c = 0; c < GC_; c++) { float d = x[c] - mu; s2 += d * d; }
    float rinv = rsqrtf(s2 * (1.f / GC_) + EPS_);
    float off0 = 0.f, off1 = 0.f;
#pragma unroll
    for (int c = 0; c < GC_; c++) {
        float xn  = (x[c] - mu) * rinv * ln_w[c] + ln_b[c];
        float gel = 0.5f * xn * (1.f + erff(xn * 0.7071067811865476f));
        off0 += pw_w[c] * gel;          // y
        off1 += pw_w[GC_ + c] * gel;    // x
    }
    const float rng = 4.0f / 31.0f;
    float py = tanhf(off0) * rng + ((0.5f + (float)h) / 31.f) * 2.f - 1.f;
    float px = tanhf(off1) * rng + ((0.5f + (float)w) / 31.f) * 2.f - 1.f;
    g_pos[idx * 2 + 0] = py;
    g_pos[idx * 2 + 1] = px;
}

// ============================================================
// Deformable bilinear sampling of kv features
// ============================================================
__global__ void sample_kernel(const float* __restrict__ kv) {
    int blk = blockIdx.x;                 // bg*N + p
    int c = threadIdx.x;
    int bg = blk >> 10, p = blk & (N_ - 1);
    int b = bg >> 2, g = bg & 3;
    float py = g_pos[blk * 2 + 0], px = g_pos[blk * 2 + 1];
    float ix = (px + 1.f) * 15.5f;
    float iy = (py + 1.f) * 15.5f;
    float x0f = floorf(ix), y0f = floorf(iy);
    float wx1 = ix - x0f, wx0 = 1.f - wx1;
    float wy1 = iy - y0f, wy0 = 1.f - wy1;
    int x0 = (int)x0f, y0 = (int)y0f;
    const float* src = kv + ((size_t)b * C_ + g * GC_ + c) * N_;
    float acc = 0.f;
#pragma unroll
    for (int cy = 0; cy < 2; cy++) {
        int yy = y0 + cy;
        if (yy < 0 || yy >= H_) continue;
        float wy = cy ? wy1 : wy0;
#pragma unroll
        for (int cx = 0; cx < 2; cx++) {
            int xx = x0 + cx;
            if (xx < 0 || xx >= W_) continue;
            acc += wy * (cx ? wx1 : wx0) * src[yy * W_ + xx];
        }
    }
    g_xs[((size_t)b * C_ + g * GC_ + c) * N_ + p] = acc;
}

// ============================================================
// Fused flash attention: S = scale*Q^T K + rpe_bias, online softmax, O = P V.
// Block: one (bh, 64-row m-tile). 256 threads (16x16), 4x4 S regs/thread.
// No materialized attention matrix.
// ============================================================
__global__ __launch_bounds__(256, 2) void flash_kernel(const float* __restrict__ rpe) {
    __shared__ float qs[32][68];       // [c][m]
    __shared__ float ks[32][68];       // [c][n]
    __shared__ float vs[32][68];       // [c][n]
    __shared__ float ps[64][68];       // [m][n] probabilities (reused for output transpose)
    __shared__ float pyn[64], pxn[64]; // 15.5*pos for current n-tile

    int tid = threadIdx.x;
    int tx = tid & 15, ty = tid >> 4;
    int bh = blockIdx.y, b = bh >> 3, hd = bh & 7;
    int m0 = blockIdx.x << 6;

    const float* qb = g_q + (size_t)(b * C_ + hd * HC_) * N_;
    const float* kb = g_k + (size_t)(b * C_ + hd * HC_) * N_;
    const float* vb = g_v + (size_t)(b * C_ + hd * HC_) * N_;
    int bg = b * NG_ + (hd >> 1);
    const float* tb = rpe + hd * 63 * 63;

    // load q tile, pre-scaled by SCALE
    for (int i = tid; i < 512; i += 256) {
        int c = i >> 4, col = (i & 15) << 2;
        float4 v = *(const float4*)&qb[(size_t)c * N_ + m0 + col];
        v.x *= SCALE_; v.y *= SCALE_; v.z *= SCALE_; v.w *= SCALE_;
        *(float4*)&qs[c][col] = v;
    }

    // per-m bias coords: ix = ax - 15.5*posx, iy = ay - 15.5*posy
    float ax[4], ay[4];
#pragma unroll
    for (int i = 0; i < 4; i++) {
        int m = m0 + (ty << 2) + i;
        ay[i] = 15.5f + (float)(m >> 5);
        ax[i] = 15.5f + (float)(m & 31);
    }

    float runm[4] = {-1e30f, -1e30f, -1e30f, -1e30f};
    float rsum[4] = {};
    float o0a[4] = {}, o1a[4] = {};   // channels c = tx and c = tx+16

    for (int nt = 0; nt < 16; nt++) {
        int n0 = nt << 6;
        __syncthreads();   // prev PV done before overwriting ks/vs
        for (int i = tid; i < 512; i += 256) {
            int c = i >> 4, col = (i & 15) << 2;
            *(float4*)&ks[c][col] = *(const float4*)&kb[(size_t)c * N_ + n0 + col];
            *(float4*)&vs[c][col] = *(const float4*)&vb[(size_t)c * N_ + n0 + col];
        }
        if (tid < 64) {
            pyn[tid] = 15.5f * g_pos[((size_t)bg * N_ + n0 + tid) * 2 + 0];
            pxn[tid] = 15.5f * g_pos[((size_t)bg * N_ + n0 + tid) * 2 + 1];
        }
        __syncthreads();

        // S = (scaled Q)^T K
        float s[4][4] = {};
#pragma unroll
        for (int c = 0; c < 32; c++) {
            float4 qv = *(const float4*)&qs[c][ty << 2];
            float4 kv = *(const float4*)&ks[c][tx << 2];
            s[0][0] = fmaf(qv.x, kv.x, s[0][0]);
            s[0][1] = fmaf(qv.x, kv.y, s[0][1]);
            s[0][2] = fmaf(qv.x, kv.z, s[0][2]);
            s[0][3] = fmaf(qv.x, kv.w, s[0][3]);
            s[1][0] = fmaf(qv.y, kv.x, s[1][0]);
            s[1][1] = fmaf(qv.y, kv.y, s[1][1]);
            s[1][2] = fmaf(qv.y, kv.z, s[1][2]);
            s[1][3] = fmaf(qv.y, kv.w, s[1][3]);
            s[2][0] = fmaf(qv.z, kv.x, s[2][0]);
            s[2][1] = fmaf(qv.z, kv.y, s[2][1]);
            s[2][2] = fmaf(qv.z, kv.z, s[2][2]);
            s[2][3] = fmaf(qv.z, kv.w, s[2][3]);
            s[3][0] = fmaf(qv.w, kv.x, s[3][0]);
            s[3][1] = fmaf(qv.w, kv.y, s[3][1]);
            s[3][2] = fmaf(qv.w, kv.z, s[3][2]);
            s[3][3] = fmaf(qv.w, kv.w, s[3][3]);
        }

        // + rpe bias (bilinear, align_corners, zeros pad)
#pragma unroll
        for (int j = 0; j < 4; j++) {
            int nn = (tx << 2) + j;
            float bx = pxn[nn], by = pyn[nn];
#pragma unroll
            for (int i = 0; i < 4; i++) {
                float ix = ax[i] - bx;
                float iy = ay[i] - by;
                float x0f = floorf(ix), y0f = floorf(iy);
                float wx1 = ix - x0f, wy1 = iy - y0f;
                float wx0 = 1.f - wx1, wy0 = 1.f - wy1;
                int x0 = (int)x0f, y0 = (int)y0f;
                float bsum = 0.f;
                bool xv0 = (unsigned)x0 <= 62u, xv1 = (unsigned)(x0 + 1) <= 62u;
                if ((unsigned)y0 <= 62u) {
                    const float* r0 = tb + y0 * 63;
                    if (xv0) bsum = fmaf(wy0 * wx0, r0[x0], bsum);
                    if (xv1) bsum = fmaf(wy0 * wx1, r0[x0 + 1], bsum);
                }
                if ((unsigned)(y0 + 1) <= 62u) {
                    const float* r1 = tb + (y0 + 1) * 63;
                    if (xv0) bsum = fmaf(wy1 * wx0, r1[x0], bsum);
                    if (xv1) bsum = fmaf(wy1 * wx1, r1[x0 + 1], bsum);
                }
                s[i][j] += bsum;
            }
        }

        // online softmax update (all-reduce across the 16 tx lanes of each row)
#pragma unroll
        for (int i = 0; i < 4; i++) {
            float tm = fmaxf(fmaxf(s[i][0], s[i][1]), fmaxf(s[i][2], s[i][3]));
#pragma unroll
            for (int off = 1; off < 16; off <<= 1)
                tm = fmaxf(tm, __shfl_xor_sync(0xffffffffu, tm, off));
            float nm = fmaxf(runm[i], tm);
            float corr = fexp(runm[i] - nm);
            runm[i] = nm;
            float p0v = fexp(s[i][0] - nm);
            float p1v = fexp(s[i][1] - nm);
            float p2v = fexp(s[i][2] - nm);
            float p3v = fexp(s[i][3] - nm);
            float rs = (p0v + p1v) + (p2v + p3v);
#pragma unroll
            for (int off = 1; off < 16; off <<= 1)
                rs += __shfl_xor_sync(0xffffffffu, rs, off);
            rsum[i] = rsum[i] * corr + rs;
            o0a[i] *= corr; o1a[i] *= corr;
            float4 pv = make_float4(p0v, p1v, p2v, p3v);
            *(float4*)&ps[(ty << 2) + i][tx << 2] = pv;
        }
        __syncwarp();   // ps rows we read are produced within this warp

        // O += P * V   (o[m][c] = sum_n p[m][n] v[c][n])
#pragma unroll
        for (int n4 = 0; n4 < 16; n4++) {
            float4 v0 = *(const float4*)&vs[tx][n4 << 2];
            float4 v1 = *(const float4*)&vs[tx + 16][n4 << 2];
#pragma unroll
            for (int i = 0; i < 4; i++) {
                float4 p4 = *(const float4*)&ps[(ty << 2) + i][n4 << 2];
                o0a[i] = fmaf(p4.x, v0.x, o0a[i]);
                o0a[i] = fmaf(p4.y, v0.y, o0a[i]);
                o0a[i] = fmaf(p4.z, v0.z, o0a[i]);
                o0a[i] = fmaf(p4.w, v0.w, o0a[i]);
                o1a[i] = fmaf(p4.x, v1.x, o1a[i]);
                o1a[i] = fmaf(p4.y, v1.y, o1a[i]);
                o1a[i] = fmaf(p4.z, v1.z, o1a[i]);
                o1a[i] = fmaf(p4.w, v1.w, o1a[i]);
            }
        }
    }

    // normalize, transpose via ps, write coalesced along m
    __syncthreads();
#pragma unroll
    for (int i = 0; i < 4; i++) {
        float inv = 1.f / rsum[i];
        ps[(ty << 2) + i][tx] = o0a[i] * inv;
        ps[(ty << 2) + i][tx + 16] = o1a[i] * inv;
    }
    __syncthreads();
    float* ob = g_o + (size_t)(b * C_ + hd * HC_) * N_;
    for (int i = tid; i < 2048; i += 256) {
        int c = i >> 6, m = i & 63;
        ob[(size_t)c * N_ + m0 + m] = ps[m][c];
    }
}

// ============================================================
extern "C" void kernel_launch(void* const* d_in, const int* in_sizes, int n_in,
                              void* d_out, int out_size) {
    const float* q_feat = (const float*)d_in[0];
    const float* kv_feat = (const float*)d_in[1];
    const float* Wq = (const float*)d_in[2];
    const float* bq = (const float*)d_in[3];
    const float* Wk = (const float*)d_in[4];
    const float* bk = (const float*)d_in[5];
    const float* Wv = (const float*)d_in[6];
    const float* bv = (const float*)d_in[7];
    const float* Wo = (const float*)d_in[8];
    const float* bo = (const float*)d_in[9];
    const float* dw_w = (const float*)d_in[10];
    const float* dw_b = (const float*)d_in[11];
    const float* ln_w = (const float*)d_in[12];
    const float* ln_b = (const float*)d_in[13];
    const float* pw_w = (const float*)d_in[14];
    const float* rpe  = (const float*)d_in[15];
    float* out = (float*)d_out;

    float *gq, *gxs, *gk, *gv, *go;
    cudaGetSymbolAddress((void**)&gq,  g_q);
    cudaGetSymbolAddress((void**)&gxs, g_xs);
    cudaGetSymbolAddress((void**)&gk,  g_k);
    cudaGetSymbolAddress((void**)&gv,  g_v);
    cudaGetSymbolAddress((void**)&go,  g_o);

    dim3 gemm_grid(N_ / 64, C_ / 64, B_);

    // 1. q projection
    gemm_proj<<<gemm_grid, 256>>>(Wq, bq, q_feat, gq);
    // 2. offset network -> pos
    offset_kernel<<<(BG_ * N_ + 255) / 256, 256>>>(dw_w, dw_b, ln_w, ln_b, pw_w);
    // 3. deformable sampling of kv
    sample_kernel<<<BG_ * N_, GC_>>>(kv_feat);
    // 4. k, v projections
    gemm_proj<<<gemm_grid, 256>>>(Wk, bk, gxs, gk);
    gemm_proj<<<gemm_grid, 256>>>(Wv, bv, gxs, gv);
    // 5-7. fused scores + bias + softmax + AV
    flash_kernel<<<dim3(N_ / 64, B_ * NH_), 256>>>(rpe);
    // 8. output projection
    gemm_proj<<<gemm_grid, 256>>>(Wo, bo, go, out);
}